// round 12
// baseline (speedup 1.0000x reference)
#include <cuda_runtime.h>
#include <cuda_fp16.h>

typedef unsigned int u32;

#define NAB 36

// Scratch (__device__ global; no allocation allowed)
__device__ __align__(256) __half g_W[NAB * 64 * 64];  // W fp16 [ab][co][ci]

__device__ __forceinline__ u32 smem_u32(const void* p) {
    u32 a;
    asm("{ .reg .u64 t; cvta.to.shared.u64 t, %1; cvt.u32.u64 %0, t; }" : "=r"(a) : "l"(p));
    return a;
}
__device__ __forceinline__ void cp16(u32 dst, const void* src) {
    asm volatile("cp.async.cg.shared.global [%0], [%1], 16;" :: "r"(dst), "l"(src) : "memory");
}
__device__ __forceinline__ void ldmx4(u32* r, u32 addr) {
    asm volatile("ldmatrix.sync.aligned.m8n8.x4.shared.b16 {%0,%1,%2,%3}, [%4];"
        : "=r"(r[0]), "=r"(r[1]), "=r"(r[2]), "=r"(r[3]) : "r"(addr));
}
__device__ __forceinline__ void ldmx2(u32* r, u32 addr) {
    asm volatile("ldmatrix.sync.aligned.m8n8.x2.shared.b16 {%0,%1}, [%2];"
        : "=r"(r[0]), "=r"(r[1]) : "r"(addr));
}
__device__ __forceinline__ void mma16f(float* d, const u32* a, const u32* b) {
    asm volatile(
        "mma.sync.aligned.m16n8k16.row.col.f32.f16.f16.f32 "
        "{%0,%1,%2,%3}, {%4,%5,%6,%7}, {%8,%9}, {%0,%1,%2,%3};"
        : "+f"(d[0]), "+f"(d[1]), "+f"(d[2]), "+f"(d[3])
        : "r"(a[0]), "r"(a[1]), "r"(a[2]), "r"(a[3]), "r"(b[0]), "r"(b[1]));
}

// ---------------------------------------------------------------------------
// K1: weight prep  weight[co][ci][ab] -> fp16 [ab][co][ci]
// ---------------------------------------------------------------------------
__global__ __launch_bounds__(256) void wt_kernel(const float* __restrict__ w) {
    int idx = blockIdx.x * 256 + threadIdx.x;      // ab*4096 + co*64 + ci
    if (idx >= NAB * 64 * 64) return;
    int ci = idx & 63;
    int co = (idx >> 6) & 63;
    int ab = idx >> 12;
    g_W[idx] = __float2half_rn(w[(co * 64 + ci) * 36 + ab]);
}

// ---------------------------------------------------------------------------
// K2: MEGA kernel, 512 threads = 16 warps (2 mw x 8 nw), warp tile 16m x 8co.
// Phase 0: input transform into smem V_s (4 iterations, 8 q-tiles each).
// Phase 1: GEMM + output transform, ZERO block barriers (per-warp W staging).
// SMEM: V_s[36][32][72]h (166KB) + per-warp 3-stage W buffers (55KB);
// sx (6x34x64 f32, 52KB, phase 0) overlays the W-buffer region.
// ---------------------------------------------------------------------------
#define VS_PLANE  4608                        // bytes per V plane = 32 rows * 144
#define OVL_OFF   (36 * VS_PLANE)             // 165888
#define WBUF_ST   1152                        // per-stage: 8 rows * 144 B
#define NSTW      3
#define WBUF_WARP (NSTW * WBUF_ST)            // 3456 per warp
#define GSM_TOTAL (OVL_OFF + 16 * WBUF_WARP)  // 221184 bytes
#define SX_PITCH  205                         // floats per ci (6*34 + 1)

__global__ __launch_bounds__(512, 1) void mega_kernel(const float* __restrict__ x,
                                                      const float* __restrict__ bias,
                                                      float* __restrict__ y) {
    extern __shared__ char sm[];
    float* sx = (float*)(sm + OVL_OFF);       // 64 * 205 f32 = 52480 B
    const int tid = threadIdx.x;
    const int m0 = blockIdx.x * 32;
    const int n = m0 >> 10;
    const int p = (m0 >> 5) & 31;
    const u32 sb0 = smem_u32(sm);

    // ================= phase 0: input transform into V_s =================
    for (int qb2 = 0; qb2 < 4; qb2++) {
        {
            int h0 = p * 4 - 1;
            int w0 = qb2 * 32 - 1;
            // stage x region: 6h x 34w x 64ci = 13056 floats
            for (int k = 0; k < 26; k++) {
                int f = k * 512 + tid;
                if (f < 13056) {
                    int wl = f % 34;
                    int u  = f / 34;
                    int hl = u % 6;
                    int ci = u / 6;
                    int gh = h0 + hl, gw = w0 + wl;
                    float val = 0.0f;
                    if ((unsigned)gh < 128u && (unsigned)gw < 128u)
                        val = x[((size_t)(n * 64 + ci) * 128 + gh) * 128 + gw];
                    sx[ci * SX_PITCH + hl * 34 + wl] = val;
                }
            }
        }
        __syncthreads();

        {
            int ci = tid & 63;
            int qt = tid >> 6;               // 0..7
            int q  = qb2 * 8 + qt;
            const float* dp = &sx[ci * SX_PITCH + qt * 4];

            float d[6][6];
#pragma unroll
            for (int i = 0; i < 6; i++)
#pragma unroll
                for (int j = 0; j < 6; j++)
                    d[i][j] = dp[i * 34 + j];

            float t[6][6];
#pragma unroll
            for (int j = 0; j < 6; j++) {
                t[0][j] =  4.0f * d[0][j] - 5.0f * d[2][j] + d[4][j];
                t[1][j] = -4.0f * d[1][j] - 4.0f * d[2][j] + d[3][j] + d[4][j];
                t[2][j] =  4.0f * d[1][j] - 4.0f * d[2][j] - d[3][j] + d[4][j];
                t[3][j] = -2.0f * d[1][j] - 1.0f * d[2][j] + 2.0f * d[3][j] + d[4][j];
                t[4][j] =  2.0f * d[1][j] - 1.0f * d[2][j] - 2.0f * d[3][j] + d[4][j];
                t[5][j] =  4.0f * d[1][j] - 5.0f * d[3][j] + d[5][j];
            }

#pragma unroll
            for (int a = 0; a < 6; a++) {
                float v[6];
                v[0] =  4.0f * t[a][0] - 5.0f * t[a][2] + t[a][4];
                v[1] = -4.0f * t[a][1] - 4.0f * t[a][2] + t[a][3] + t[a][4];
                v[2] =  4.0f * t[a][1] - 4.0f * t[a][2] - t[a][3] + t[a][4];
                v[3] = -2.0f * t[a][1] - 1.0f * t[a][2] + 2.0f * t[a][3] + t[a][4];
                v[4] =  2.0f * t[a][1] - 1.0f * t[a][2] - 2.0f * t[a][3] + t[a][4];
                v[5] =  4.0f * t[a][1] - 5.0f * t[a][3] + t[a][5];
#pragma unroll
                for (int bb = 0; bb < 6; bb++)
                    *(__half*)(sm + (a * 6 + bb) * VS_PLANE + q * 144 + ci * 2) =
                        __float2half_rn(v[bb]);
            }
        }
        __syncthreads();   // V_s writes done; sx free for next iteration
    }
    // V_s finalized for ALL warps.

    // ====== phase 1: GEMM + output transform (no block barriers) ======
    const int wid = tid >> 5, lane = tid & 31;
    const int g = lane >> 2, t4 = lane & 3;
    const int mw = wid & 1;            // 2 m-warps x 16 rows
    const int nw = wid >> 1;           // 8 co-warps x 8 cols
    const int warpM = mw * 16;
    const int warpN = nw * 8;

    const u32 wbuf = sb0 + OVL_OFF + (u32)wid * WBUF_WARP;

    // per-warp W fill: 8 co rows x 64 k halfs -> stage (idx % 3)
    auto wfill = [&](int idx) {
        int a = idx % 6, b = idx / 6;
        const __half* wp = g_W + (a * 6 + b) * 4096 + warpN * 64;
        u32 dst = wbuf + (u32)(idx % NSTW) * WBUF_ST;
#pragma unroll
        for (int i = 0; i < 2; i++) {
            int t = lane + i * 32;        // 0..63 tasks of 16 B
            int r = t >> 3, c = t & 7;
            cp16(dst + (u32)(r * 144 + c * 16), wp + r * 64 + c * 8);
        }
        asm volatile("cp.async.commit_group;" ::: "memory");
    };

    // A ldmatrix lane offset (within a V plane)
    const u32 aOff = (u32)((warpM + (lane & 15)) * 144 + (lane >> 4) * 16);
    // B ldmatrix.x2 lane offset within the warp's W stage (8 local co rows)
    const int bl = lane & 15;
    const u32 bOff = (u32)(((bl & 7)) * 144 + ((bl >> 3) & 1) * 16);

    float accY[4][4][4];               // [elem][x][y]
#pragma unroll
    for (int e = 0; e < 4; e++)
#pragma unroll
        for (int xx = 0; xx < 4; xx++)
#pragma unroll
            for (int yy = 0; yy < 4; yy++) accY[e][xx][yy] = 0.0f;

    wfill(0);
    wfill(1);

    for (int b = 0; b < 6; b++) {
        float Z[4][4];
#pragma unroll
        for (int e = 0; e < 4; e++)
#pragma unroll
            for (int xx = 0; xx < 4; xx++) Z[e][xx] = 0.0f;

#pragma unroll
        for (int a = 0; a < 6; a++) {
            int idx = b * 6 + a;
            if (idx + 2 < 36) wfill(idx + 2);
            int rem = 35 - idx;
            if (rem >= 2)      asm volatile("cp.async.wait_group 2;" ::: "memory");
            else if (rem == 1) asm volatile("cp.async.wait_group 1;" ::: "memory");
            else               asm volatile("cp.async.wait_group 0;" ::: "memory");
            __syncwarp();

            int plane = a * 6 + b;
            u32 abase = sb0 + (u32)(plane * VS_PLANE);
            u32 wbase = wbuf + (u32)(idx % NSTW) * WBUF_ST;

            // two independent 2-deep HMMA chains
            float dA[4] = {0, 0, 0, 0};
            float dB[4] = {0, 0, 0, 0};
#pragma unroll
            for (int ks = 0; ks < 4; ks++) {
                u32 av[4], bv2[2];
                ldmx4(av, abase + aOff + ks * 32);
                ldmx2(bv2, wbase + bOff + ks * 32);
                if (ks < 2) mma16f(dA, av, bv2);
                else        mma16f(dB, av, bv2);
            }

            // fold M_ab into Z with AT column a (compile-time coefficients)
#pragma unroll
            for (int r = 0; r < 4; r++) {
                float dd = dA[r] + dB[r];
                if (a == 0) {
                    Z[r][0] += dd;
                } else if (a == 1) {
                    Z[r][0] += dd; Z[r][1] += dd; Z[r][2] += dd; Z[r][3] += dd;
                } else if (a == 2) {
                    Z[r][0] += dd; Z[r][1] -= dd; Z[r][2] += dd; Z[r][3] -= dd;
                } else if (a == 3) {
                    Z[r][0] += dd; Z[r][1] += 2.0f * dd;
                    Z[r][2] += 4.0f * dd; Z[r][3] += 8.0f * dd;
                } else if (a == 4) {
                    Z[r][0] += dd; Z[r][1] -= 2.0f * dd;
                    Z[r][2] += 4.0f * dd; Z[r][3] -= 8.0f * dd;
                } else {
                    Z[r][3] += dd;
                }
            }
        }

        // fold Z into Y with AT column b
        float c0, c1, c2, c3;
        switch (b) {
            case 0:  c0 = 1; c1 = 0;  c2 = 0; c3 = 0;  break;
            case 1:  c0 = 1; c1 = 1;  c2 = 1; c3 = 1;  break;
            case 2:  c0 = 1; c1 = -1; c2 = 1; c3 = -1; break;
            case 3:  c0 = 1; c1 = 2;  c2 = 4; c3 = 8;  break;
            case 4:  c0 = 1; c1 = -2; c2 = 4; c3 = -8; break;
            default: c0 = 0; c1 = 0;  c2 = 0; c3 = 1;  break;
        }
#pragma unroll
        for (int e = 0; e < 4; e++)
#pragma unroll
            for (int xx = 0; xx < 4; xx++) {
                float z = Z[e][xx];
                accY[e][xx][0] += z * c0;
                accY[e][xx][1] += z * c1;
                accY[e][xx][2] += z * c2;
                accY[e][xx][3] += z * c3;
            }
    }

    // ---- epilogue: bias + direct y stores ----
#pragma unroll
    for (int e = 0; e < 4; e++) {
        int co = warpN + 2 * t4 + (e & 1);
        int mrow = warpM + g + (e >> 1) * 8;
        float bv = __ldg(&bias[co]);
        int m = m0 + mrow;
        int q = m & 31;
        float* yb = y + (((size_t)(n * 64 + co) * 128) + p * 4) * 128 + q * 4;
#pragma unroll
        for (int xx = 0; xx < 4; xx++) {
            float4 st = make_float4(accY[e][xx][0] + bv, accY[e][xx][1] + bv,
                                    accY[e][xx][2] + bv, accY[e][xx][3] + bv);
            *(float4*)(yb + xx * 128) = st;
        }
    }
}

// ---------------------------------------------------------------------------
extern "C" void kernel_launch(void* const* d_in, const int* in_sizes, int n_in,
                              void* d_out, int out_size) {
    const float* x = (const float*)d_in[0];   // (16, 64, 128, 128) f32
    const float* w = (const float*)d_in[1];   // (64, 64, 6, 6) f32
    const float* b = (const float*)d_in[2];   // (64,) f32
    float* y = (float*)d_out;                 // (16, 64, 128, 128) f32

    cudaFuncSetAttribute(mega_kernel, cudaFuncAttributeMaxDynamicSharedMemorySize,
                         GSM_TOTAL);

    wt_kernel<<<(NAB * 64 * 64 + 255) / 256, 256>>>(w);
    mega_kernel<<<512, 512, GSM_TOTAL>>>(x, b, y);
}

// round 13
// speedup vs baseline: 1.5428x; 1.5428x over previous
#include <cuda_runtime.h>
#include <cuda_fp16.h>

typedef unsigned int u32;

#define NAB 36

// Scratch (__device__ global; no allocation allowed)
__device__ __align__(256) __half g_W[NAB * 64 * 64];  // W fp16 [ab][co][ci]

__device__ __forceinline__ u32 smem_u32(const void* p) {
    u32 a;
    asm("{ .reg .u64 t; cvta.to.shared.u64 t, %1; cvt.u32.u64 %0, t; }" : "=r"(a) : "l"(p));
    return a;
}
__device__ __forceinline__ void cp16(u32 dst, const void* src) {
    asm volatile("cp.async.cg.shared.global [%0], [%1], 16;" :: "r"(dst), "l"(src) : "memory");
}
__device__ __forceinline__ void ldmx4(u32* r, u32 addr) {
    asm volatile("ldmatrix.sync.aligned.m8n8.x4.shared.b16 {%0,%1,%2,%3}, [%4];"
        : "=r"(r[0]), "=r"(r[1]), "=r"(r[2]), "=r"(r[3]) : "r"(addr));
}
__device__ __forceinline__ void mma16f(float* d, const u32* a, const u32* b) {
    asm volatile(
        "mma.sync.aligned.m16n8k16.row.col.f32.f16.f16.f32 "
        "{%0,%1,%2,%3}, {%4,%5,%6,%7}, {%8,%9}, {%0,%1,%2,%3};"
        : "+f"(d[0]), "+f"(d[1]), "+f"(d[2]), "+f"(d[3])
        : "r"(a[0]), "r"(a[1]), "r"(a[2]), "r"(a[3]), "r"(b[0]), "r"(b[1]));
}

// ---------------------------------------------------------------------------
// K1: weight prep  weight[co][ci][ab] -> fp16 [ab][co][ci]
// ---------------------------------------------------------------------------
__global__ __launch_bounds__(256) void wt_kernel(const float* __restrict__ w) {
    int idx = blockIdx.x * 256 + threadIdx.x;      // ab*4096 + co*64 + ci
    if (idx >= NAB * 64 * 64) return;
    int ci = idx & 63;
    int co = (idx >> 6) & 63;
    int ab = idx >> 12;
    g_W[idx] = __float2half_rn(w[(co * 64 + ci) * 36 + ab]);
}

// ---------------------------------------------------------------------------
// K2: MEGA kernel — phase 0: input transform into smem V_s;
// phase 1: GEMM + output transform, zero block barriers, fully unrolled
// 36-plane schedule (compile-time planes / stages / wait counts),
// butterfly a-folds.  grid 512 CTAs; 256 threads = 8 warps (2mw x 4nw),
// warp tile 16m x 16co.
// ---------------------------------------------------------------------------
#define VS_PLANE  4608                        // bytes per V plane = 32 rows * 144
#define OVL_OFF   (36 * VS_PLANE)             // 165888
#define WBUF_ST   2304                        // per-stage: 16 rows * 144 B
#define NSTW      3
#define WBUF_WARP (NSTW * WBUF_ST)            // 6912 per warp
#define GSM_TOTAL (OVL_OFF + 8 * WBUF_WARP)   // 221184 bytes

__global__ __launch_bounds__(256, 1) void mega_kernel(const float* __restrict__ x,
                                                      const float* __restrict__ bias,
                                                      float* __restrict__ y) {
    extern __shared__ char sm[];
    float* sx = (float*)(sm + OVL_OFF);       // 64*109 f32 = 27904 B (fits overlay)
    const int tid = threadIdx.x;
    const int m0 = blockIdx.x * 32;
    const int n = m0 >> 10;
    const int p = (m0 >> 5) & 31;
    const u32 sb0 = smem_u32(sm);

    // ================= phase 0: input transform into V_s =================
    for (int qb = 0; qb < 8; qb++) {
        int h0 = p * 4 - 1;
        int w0 = qb * 16 - 1;
#pragma unroll
        for (int k = 0; k < 27; k++) {
            int f = k * 256 + tid;
            int wl = f % 18;
            int u  = f / 18;
            int hl = u % 6;
            int ci = u / 6;
            int gh = h0 + hl, gw = w0 + wl;
            float val = 0.0f;
            if ((unsigned)gh < 128u && (unsigned)gw < 128u)
                val = x[((size_t)(n * 64 + ci) * 128 + gh) * 128 + gw];
            sx[ci * 109 + hl * 18 + wl] = val;
        }
        __syncthreads();

        int ci = tid & 63;
        int qt = tid >> 6;
        int q  = qb * 4 + qt;
        const float* dp = &sx[ci * 109 + qt * 4];

        float d[6][6];
#pragma unroll
        for (int i = 0; i < 6; i++)
#pragma unroll
            for (int j = 0; j < 6; j++)
                d[i][j] = dp[i * 18 + j];

        float t[6][6];
#pragma unroll
        for (int j = 0; j < 6; j++) {
            t[0][j] =  4.0f * d[0][j] - 5.0f * d[2][j] + d[4][j];
            t[1][j] = -4.0f * d[1][j] - 4.0f * d[2][j] + d[3][j] + d[4][j];
            t[2][j] =  4.0f * d[1][j] - 4.0f * d[2][j] - d[3][j] + d[4][j];
            t[3][j] = -2.0f * d[1][j] - 1.0f * d[2][j] + 2.0f * d[3][j] + d[4][j];
            t[4][j] =  2.0f * d[1][j] - 1.0f * d[2][j] - 2.0f * d[3][j] + d[4][j];
            t[5][j] =  4.0f * d[1][j] - 5.0f * d[3][j] + d[5][j];
        }

#pragma unroll
        for (int a = 0; a < 6; a++) {
            float v[6];
            v[0] =  4.0f * t[a][0] - 5.0f * t[a][2] + t[a][4];
            v[1] = -4.0f * t[a][1] - 4.0f * t[a][2] + t[a][3] + t[a][4];
            v[2] =  4.0f * t[a][1] - 4.0f * t[a][2] - t[a][3] + t[a][4];
            v[3] = -2.0f * t[a][1] - 1.0f * t[a][2] + 2.0f * t[a][3] + t[a][4];
            v[4] =  2.0f * t[a][1] - 1.0f * t[a][2] - 2.0f * t[a][3] + t[a][4];
            v[5] =  4.0f * t[a][1] - 5.0f * t[a][3] + t[a][5];
#pragma unroll
            for (int bb = 0; bb < 6; bb++)
                *(__half*)(sm + (a * 6 + bb) * VS_PLANE + q * 144 + ci * 2) =
                    __float2half_rn(v[bb]);
        }
        __syncthreads();
    }
    // V_s finalized for ALL warps.

    // ====== phase 1: GEMM + output transform (no block barriers) ======
    const int wid = tid >> 5, lane = tid & 31;
    const int g = lane >> 2, t4 = lane & 3;
    const int mw = wid & 1;            // 2 m-warps x 16 rows
    const int nq = wid >> 1;           // 4 co-warps x 16 cols
    const int warpM = mw * 16;
    const int warpN = nq * 16;

    const u32 wbuf = sb0 + OVL_OFF + (u32)wid * WBUF_WARP;

    // per-warp W fill: 16 co rows x 64 k halfs -> stage (idx % 3)
    auto wfill = [&](int idx) {
        int a = idx % 6, b = idx / 6;
        const __half* wp = g_W + (a * 6 + b) * 4096 + warpN * 64;
        u32 dst = wbuf + (u32)(idx % NSTW) * WBUF_ST;
#pragma unroll
        for (int i = 0; i < 4; i++) {
            int t = lane + i * 32;        // 0..127 tasks of 16 B
            int r = t >> 3, c = t & 7;
            cp16(dst + (u32)(r * 144 + c * 16), wp + r * 64 + c * 8);
        }
        asm volatile("cp.async.commit_group;" ::: "memory");
    };

    // A ldmatrix lane offset (within a V plane)
    const u32 aOff = (u32)((warpM + (lane & 15)) * 144 + (lane >> 4) * 16);
    // B ldmatrix.x4 lane offset within the warp's W stage (local co rows)
    const u32 bOff = (u32)(((lane & 7) + ((lane >> 4) & 1) * 8) * 144
                           + ((lane >> 3) & 1) * 16);

    float accY[8][4][4];
#pragma unroll
    for (int e = 0; e < 8; e++)
#pragma unroll
        for (int xx = 0; xx < 4; xx++)
#pragma unroll
            for (int yy = 0; yy < 4; yy++) accY[e][xx][yy] = 0.0f;

    wfill(0);
    wfill(1);

#pragma unroll
    for (int b = 0; b < 6; b++) {
        float Z[8][4];
#pragma unroll
        for (int e = 0; e < 8; e++)
#pragma unroll
            for (int xx = 0; xx < 4; xx++) Z[e][xx] = 0.0f;

        float pv[8];                   // saved d from a=1 / a=3 for butterfly

#pragma unroll
        for (int a = 0; a < 6; a++) {
            const int idx = b * 6 + a;
            if (idx + 2 < 36) wfill(idx + 2);
            const int rem = 35 - idx;
            if (rem >= 2)      asm volatile("cp.async.wait_group 2;" ::: "memory");
            else if (rem == 1) asm volatile("cp.async.wait_group 1;" ::: "memory");
            else               asm volatile("cp.async.wait_group 0;" ::: "memory");
            __syncwarp();

            const int plane = a * 6 + b;
            const u32 abase = sb0 + (u32)(plane * VS_PLANE);
            const u32 wbase = wbuf + (u32)(idx % NSTW) * WBUF_ST;

            float d1[4] = {0, 0, 0, 0};
            float d2[4] = {0, 0, 0, 0};
#pragma unroll
            for (int ks = 0; ks < 4; ks++) {
                u32 av[4], bv4[4];
                ldmx4(av, abase + aOff + ks * 32);
                ldmx4(bv4, wbase + bOff + ks * 32);
                mma16f(d1, av, bv4);        // co group 0
                mma16f(d2, av, bv4 + 2);    // co group 1
            }

            // fold M_ab into Z with AT column a (compile-time a, butterflies)
#pragma unroll
            for (int j = 0; j < 2; j++)
#pragma unroll
                for (int r = 0; r < 4; r++) {
                    const int e = j * 4 + r;
                    float dd = (j == 0) ? d1[r] : d2[r];
                    if (a == 0) {
                        Z[e][0] += dd;
                    } else if (a == 1 || a == 3) {
                        pv[e] = dd;                 // defer to butterfly
                    } else if (a == 2) {
                        float s = pv[e] + dd;
                        float t = pv[e] - dd;
                        Z[e][0] += s; Z[e][2] += s;
                        Z[e][1] += t; Z[e][3] += t;
                    } else if (a == 4) {
                        float s = pv[e] + dd;
                        float t = pv[e] - dd;
                        Z[e][0] += s;              Z[e][2] += 4.0f * s;
                        Z[e][1] += 2.0f * t;       Z[e][3] += 8.0f * t;
                    } else {
                        Z[e][3] += dd;
                    }
                }
        }

        // fold Z into Y with AT column b (compile-time b; zeros eliminated)
#pragma unroll
        for (int e = 0; e < 8; e++)
#pragma unroll
            for (int xx = 0; xx < 4; xx++) {
                float z = Z[e][xx];
                if (b == 0) {
                    accY[e][xx][0] += z;
                } else if (b == 1) {
                    accY[e][xx][0] += z; accY[e][xx][1] += z;
                    accY[e][xx][2] += z; accY[e][xx][3] += z;
                } else if (b == 2) {
                    accY[e][xx][0] += z; accY[e][xx][1] -= z;
                    accY[e][xx][2] += z; accY[e][xx][3] -= z;
                } else if (b == 3) {
                    accY[e][xx][0] += z;          accY[e][xx][1] += 2.0f * z;
                    accY[e][xx][2] += 4.0f * z;   accY[e][xx][3] += 8.0f * z;
                } else if (b == 4) {
                    accY[e][xx][0] += z;          accY[e][xx][1] -= 2.0f * z;
                    accY[e][xx][2] += 4.0f * z;   accY[e][xx][3] -= 8.0f * z;
                } else {
                    accY[e][xx][3] += z;
                }
            }
    }

    // ---- epilogue: bias + direct y stores ----
#pragma unroll
    for (int e = 0; e < 8; e++) {
        int j = e >> 2, r = e & 3;
        int co = warpN + j * 8 + 2 * t4 + (r & 1);
        int mrow = warpM + g + (r >> 1) * 8;
        float bv = __ldg(&bias[co]);
        int m = m0 + mrow;
        int q = m & 31;
        float* yb = y + (((size_t)(n * 64 + co) * 128) + p * 4) * 128 + q * 4;
#pragma unroll
        for (int xx = 0; xx < 4; xx++) {
            float4 st = make_float4(accY[e][xx][0] + bv, accY[e][xx][1] + bv,
                                    accY[e][xx][2] + bv, accY[e][xx][3] + bv);
            *(float4*)(yb + xx * 128) = st;
        }
    }
}

// ---------------------------------------------------------------------------
extern "C" void kernel_launch(void* const* d_in, const int* in_sizes, int n_in,
                              void* d_out, int out_size) {
    const float* x = (const float*)d_in[0];   // (16, 64, 128, 128) f32
    const float* w = (const float*)d_in[1];   // (64, 64, 6, 6) f32
    const float* b = (const float*)d_in[2];   // (64,) f32
    float* y = (float*)d_out;                 // (16, 64, 128, 128) f32

    cudaFuncSetAttribute(mega_kernel, cudaFuncAttributeMaxDynamicSharedMemorySize,
                         GSM_TOTAL);

    wt_kernel<<<(NAB * 64 * 64 + 255) / 256, 256>>>(w);
    mega_kernel<<<512, 256, GSM_TOTAL>>>(x, b, y);
}

// round 14
// speedup vs baseline: 1.7787x; 1.1529x over previous
#include <cuda_runtime.h>
#include <cuda_fp16.h>

typedef unsigned int u32;

#define NAB 36

// Scratch (__device__ global; no allocation allowed)
__device__ __align__(256) __half g_W[NAB * 64 * 64];  // W fp16 [ab][co][ci]

__device__ __forceinline__ u32 smem_u32(const void* p) {
    u32 a;
    asm("{ .reg .u64 t; cvta.to.shared.u64 t, %1; cvt.u32.u64 %0, t; }" : "=r"(a) : "l"(p));
    return a;
}
__device__ __forceinline__ void cp16(u32 dst, const void* src) {
    asm volatile("cp.async.cg.shared.global [%0], [%1], 16;" :: "r"(dst), "l"(src) : "memory");
}
__device__ __forceinline__ void ldmx4(u32* r, u32 addr) {
    asm volatile("ldmatrix.sync.aligned.m8n8.x4.shared.b16 {%0,%1,%2,%3}, [%4];"
        : "=r"(r[0]), "=r"(r[1]), "=r"(r[2]), "=r"(r[3]) : "r"(addr));
}
__device__ __forceinline__ void ldmx2(u32* r, u32 addr) {
    asm volatile("ldmatrix.sync.aligned.m8n8.x2.shared.b16 {%0,%1}, [%2];"
        : "=r"(r[0]), "=r"(r[1]) : "r"(addr));
}
__device__ __forceinline__ void mma16f(float* d, const u32* a, const u32* b) {
    asm volatile(
        "mma.sync.aligned.m16n8k16.row.col.f32.f16.f16.f32 "
        "{%0,%1,%2,%3}, {%4,%5,%6,%7}, {%8,%9}, {%0,%1,%2,%3};"
        : "+f"(d[0]), "+f"(d[1]), "+f"(d[2]), "+f"(d[3])
        : "r"(a[0]), "r"(a[1]), "r"(a[2]), "r"(a[3]), "r"(b[0]), "r"(b[1]));
}

// ---------------------------------------------------------------------------
// K1: weight prep  weight[co][ci][ab] -> fp16 [ab][co][ci]
// ---------------------------------------------------------------------------
__global__ __launch_bounds__(256) void wt_kernel(const float* __restrict__ w) {
    int idx = blockIdx.x * 256 + threadIdx.x;      // ab*4096 + co*64 + ci
    if (idx >= NAB * 64 * 64) return;
    int ci = idx & 63;
    int co = (idx >> 6) & 63;
    int ab = idx >> 12;
    g_W[idx] = __float2half_rn(w[(co * 64 + ci) * 36 + ab]);
}

// ---------------------------------------------------------------------------
// K2: MEGA kernel, m-tile 16 (grid 1024), 256 threads = 8 warps, warp tile
// 16m x 8co.  Phase 0: input transform into smem V_s (4 chunks).
// Phase 1: GEMM + output transform, zero block barriers (per-warp W staging).
// SMEM total 110848 B -> 2 CTAs/SM (regs capped at 128 via launch_bounds).
// ---------------------------------------------------------------------------
#define VS_PLANE  2304                        // bytes per V plane = 16 rows * 144
#define OVL_OFF   (36 * VS_PLANE)             // 82944
#define WBUF_ST   1152                        // per-stage: 8 rows * 144 B
#define NSTW      3
#define WBUF_WARP (NSTW * WBUF_ST)            // 3456 per warp (8 warps = 27648)
#define SX_BYTES  (64 * 109 * 4)              // 27904 (overlay, >= W bufs)
#define GSM_TOTAL (OVL_OFF + SX_BYTES)        // 110848 bytes

__global__ __launch_bounds__(256, 2) void mega_kernel(const float* __restrict__ x,
                                                      const float* __restrict__ bias,
                                                      float* __restrict__ y) {
    extern __shared__ char sm[];
    float* sx = (float*)(sm + OVL_OFF);       // 64*109 f32, phase-0 only
    const int tid = threadIdx.x;
    const int m0 = blockIdx.x * 16;
    const int n = m0 >> 10;
    const int p = (m0 >> 5) & 31;
    const int q0 = m0 & 31;                   // 0 or 16
    const u32 sb0 = smem_u32(sm);

    // ================= phase 0: input transform into V_s =================
    for (int qc = 0; qc < 4; qc++) {
        int h0 = p * 4 - 1;
        int w0 = (q0 + qc * 4) * 4 - 1;
#pragma unroll
        for (int k = 0; k < 27; k++) {
            int f = k * 256 + tid;
            int wl = f % 18;
            int u  = f / 18;
            int hl = u % 6;
            int ci = u / 6;
            int gh = h0 + hl, gw = w0 + wl;
            float val = 0.0f;
            if ((unsigned)gh < 128u && (unsigned)gw < 128u)
                val = x[((size_t)(n * 64 + ci) * 128 + gh) * 128 + gw];
            sx[ci * 109 + hl * 18 + wl] = val;
        }
        __syncthreads();

        int ci = tid & 63;
        int qt = tid >> 6;                    // 0..3
        int ql = qc * 4 + qt;                 // local V row 0..15
        const float* dp = &sx[ci * 109 + qt * 4];

        float d[6][6];
#pragma unroll
        for (int i = 0; i < 6; i++)
#pragma unroll
            for (int j = 0; j < 6; j++)
                d[i][j] = dp[i * 18 + j];

        float t[6][6];
#pragma unroll
        for (int j = 0; j < 6; j++) {
            t[0][j] =  4.0f * d[0][j] - 5.0f * d[2][j] + d[4][j];
            t[1][j] = -4.0f * d[1][j] - 4.0f * d[2][j] + d[3][j] + d[4][j];
            t[2][j] =  4.0f * d[1][j] - 4.0f * d[2][j] - d[3][j] + d[4][j];
            t[3][j] = -2.0f * d[1][j] - 1.0f * d[2][j] + 2.0f * d[3][j] + d[4][j];
            t[4][j] =  2.0f * d[1][j] - 1.0f * d[2][j] - 2.0f * d[3][j] + d[4][j];
            t[5][j] =  4.0f * d[1][j] - 5.0f * d[3][j] + d[5][j];
        }

#pragma unroll
        for (int a = 0; a < 6; a++) {
            float v[6];
            v[0] =  4.0f * t[a][0] - 5.0f * t[a][2] + t[a][4];
            v[1] = -4.0f * t[a][1] - 4.0f * t[a][2] + t[a][3] + t[a][4];
            v[2] =  4.0f * t[a][1] - 4.0f * t[a][2] - t[a][3] + t[a][4];
            v[3] = -2.0f * t[a][1] - 1.0f * t[a][2] + 2.0f * t[a][3] + t[a][4];
            v[4] =  2.0f * t[a][1] - 1.0f * t[a][2] - 2.0f * t[a][3] + t[a][4];
            v[5] =  4.0f * t[a][1] - 5.0f * t[a][3] + t[a][5];
#pragma unroll
            for (int bb = 0; bb < 6; bb++)
                *(__half*)(sm + (a * 6 + bb) * VS_PLANE + ql * 144 + ci * 2) =
                    __float2half_rn(v[bb]);
        }
        __syncthreads();
    }
    // V_s finalized for ALL warps.

    // ====== phase 1: GEMM + output transform (no block barriers) ======
    const int wid = tid >> 5, lane = tid & 31;
    const int g = lane >> 2, t4 = lane & 3;
    const int warpN = wid * 8;                // 8 co-warps x 8 cols

    const u32 wbuf = sb0 + OVL_OFF + (u32)wid * WBUF_WARP;

    // per-warp W fill: 8 co rows x 64 k halfs -> stage (idx % 3)
    auto wfill = [&](int idx) {
        int a = idx % 6, b = idx / 6;
        const __half* wp = g_W + (a * 6 + b) * 4096 + warpN * 64;
        u32 dst = wbuf + (u32)(idx % NSTW) * WBUF_ST;
#pragma unroll
        for (int i = 0; i < 2; i++) {
            int t = lane + i * 32;            // 0..63 tasks of 16 B
            int r = t >> 3, c = t & 7;
            cp16(dst + (u32)(r * 144 + c * 16), wp + r * 64 + c * 8);
        }
        asm volatile("cp.async.commit_group;" ::: "memory");
    };

    // A ldmatrix lane offset (16 rows per V plane)
    const u32 aOff = (u32)((lane & 15) * 144 + (lane >> 4) * 16);
    // B ldmatrix.x2 lane offset within the warp's W stage (8 local co rows)
    const int bl = lane & 15;
    const u32 bOff = (u32)((bl & 7) * 144 + ((bl >> 3) & 1) * 16);

    float accY[4][4][4];                      // [elem][x][y]
#pragma unroll
    for (int e = 0; e < 4; e++)
#pragma unroll
        for (int xx = 0; xx < 4; xx++)
#pragma unroll
            for (int yy = 0; yy < 4; yy++) accY[e][xx][yy] = 0.0f;

    wfill(0);
    wfill(1);

    for (int b = 0; b < 6; b++) {
        float Z[4][4];
#pragma unroll
        for (int e = 0; e < 4; e++)
#pragma unroll
            for (int xx = 0; xx < 4; xx++) Z[e][xx] = 0.0f;

#pragma unroll
        for (int a = 0; a < 6; a++) {
            int idx = b * 6 + a;
            if (idx + 2 < 36) wfill(idx + 2);
            int rem = 35 - idx;
            if (rem >= 2)      asm volatile("cp.async.wait_group 2;" ::: "memory");
            else if (rem == 1) asm volatile("cp.async.wait_group 1;" ::: "memory");
            else               asm volatile("cp.async.wait_group 0;" ::: "memory");
            __syncwarp();

            int plane = a * 6 + b;
            u32 abase = sb0 + (u32)(plane * VS_PLANE);
            u32 wbase = wbuf + (u32)(idx % NSTW) * WBUF_ST;

            // two independent 2-deep HMMA chains
            float dA[4] = {0, 0, 0, 0};
            float dB[4] = {0, 0, 0, 0};
#pragma unroll
            for (int ks = 0; ks < 4; ks++) {
                u32 av[4], bv2[2];
                ldmx4(av, abase + aOff + ks * 32);
                ldmx2(bv2, wbase + bOff + ks * 32);
                if (ks < 2) mma16f(dA, av, bv2);
                else        mma16f(dB, av, bv2);
            }

            // fold M_ab into Z with AT column a (compile-time coefficients)
#pragma unroll
            for (int r = 0; r < 4; r++) {
                float dd = dA[r] + dB[r];
                if (a == 0) {
                    Z[r][0] += dd;
                } else if (a == 1) {
                    Z[r][0] += dd; Z[r][1] += dd; Z[r][2] += dd; Z[r][3] += dd;
                } else if (a == 2) {
                    Z[r][0] += dd; Z[r][1] -= dd; Z[r][2] += dd; Z[r][3] -= dd;
                } else if (a == 3) {
                    Z[r][0] += dd; Z[r][1] += 2.0f * dd;
                    Z[r][2] += 4.0f * dd; Z[r][3] += 8.0f * dd;
                } else if (a == 4) {
                    Z[r][0] += dd; Z[r][1] -= 2.0f * dd;
                    Z[r][2] += 4.0f * dd; Z[r][3] -= 8.0f * dd;
                } else {
                    Z[r][3] += dd;
                }
            }
        }

        // fold Z into Y with AT column b
        float c0, c1, c2, c3;
        switch (b) {
            case 0:  c0 = 1; c1 = 0;  c2 = 0; c3 = 0;  break;
            case 1:  c0 = 1; c1 = 1;  c2 = 1; c3 = 1;  break;
            case 2:  c0 = 1; c1 = -1; c2 = 1; c3 = -1; break;
            case 3:  c0 = 1; c1 = 2;  c2 = 4; c3 = 8;  break;
            case 4:  c0 = 1; c1 = -2; c2 = 4; c3 = -8; break;
            default: c0 = 0; c1 = 0;  c2 = 0; c3 = 1;  break;
        }
#pragma unroll
        for (int e = 0; e < 4; e++)
#pragma unroll
            for (int xx = 0; xx < 4; xx++) {
                float z = Z[e][xx];
                accY[e][xx][0] += z * c0;
                accY[e][xx][1] += z * c1;
                accY[e][xx][2] += z * c2;
                accY[e][xx][3] += z * c3;
            }
    }

    // ---- epilogue: bias + direct y stores ----
#pragma unroll
    for (int e = 0; e < 4; e++) {
        int co = warpN + 2 * t4 + (e & 1);
        int mrow = g + (e >> 1) * 8;          // 0..15
        float bv = __ldg(&bias[co]);
        int m = m0 + mrow;
        int qq = m & 31;
        float* yb = y + (((size_t)(n * 64 + co) * 128) + p * 4) * 128 + qq * 4;
#pragma unroll
        for (int xx = 0; xx < 4; xx++) {
            float4 st = make_float4(accY[e][xx][0] + bv, accY[e][xx][1] + bv,
                                    accY[e][xx][2] + bv, accY[e][xx][3] + bv);
            *(float4*)(yb + xx * 128) = st;
        }
    }
}

// ---------------------------------------------------------------------------
extern "C" void kernel_launch(void* const* d_in, const int* in_sizes, int n_in,
                              void* d_out, int out_size) {
    const float* x = (const float*)d_in[0];   // (16, 64, 128, 128) f32
    const float* w = (const float*)d_in[1];   // (64, 64, 6, 6) f32
    const float* b = (const float*)d_in[2];   // (64,) f32
    float* y = (float*)d_out;                 // (16, 64, 128, 128) f32

    cudaFuncSetAttribute(mega_kernel, cudaFuncAttributeMaxDynamicSharedMemorySize,
                         GSM_TOTAL);

    wt_kernel<<<(NAB * 64 * 64 + 255) / 256, 256>>>(w);
    mega_kernel<<<1024, 256, GSM_TOTAL>>>(x, b, y);
}